// round 1
// baseline (speedup 1.0000x reference)
#include <cuda_runtime.h>

#define BB 2
#define C 256
#define NH 8
#define HD 32
#define NN 4096
#define ATT_SCALE 0.17677669529663687f  // 32^-0.5

// Scratch: [src][batch][plane Q/K/V][c][n]  (48 MB) and per-branch attention
// output [branch][batch][c][n] (16 MB). __device__ globals per harness rules.
__device__ float g_qkv[2][BB][3][C][NN];
__device__ float g_attn[2][BB][C][NN];

// ---------------------------------------------------------------------------
// Projection GEMM: Y[o,n] = sum_c W[o,c] * X[c,n] + bias[o]
// 64x64 tile per block, 256 threads, 4x4 microtile, K-chunk 32.
// grid: (N/64, C/64, 12) with z = ((src*2+b)*3 + plane)
// ---------------------------------------------------------------------------
__global__ void proj_kernel(const float* __restrict__ xs,
                            const float* __restrict__ xf,
                            const float* __restrict__ wq, const float* __restrict__ bq,
                            const float* __restrict__ wk, const float* __restrict__ bk,
                            const float* __restrict__ wv, const float* __restrict__ bv)
{
    int zz = blockIdx.z;
    int plane = zz % 3;
    int sb = zz / 3;
    int b = sb & 1;
    int src = sb >> 1;
    const float* x = (src ? xf : xs) + (size_t)b * C * NN;
    const float* w; const float* bias;
    if (plane == 0)      { w = wq; bias = bq; }
    else if (plane == 1) { w = wk; bias = bk; }
    else                 { w = wv; bias = bv; }
    float* y = &g_qkv[src][b][plane][0][0];

    int o0 = blockIdx.y * 64;
    int n0 = blockIdx.x * 64;

    __shared__ float As[64][33];   // W tile [o][kk], padded
    __shared__ float Bs[32][64];   // X tile [kk][n]

    int t  = threadIdx.x;          // 256 threads
    int tx = t & 15, ty = t >> 4;
    float acc[4][4] = {};

    for (int c0 = 0; c0 < C; c0 += 32) {
        for (int i = t; i < 64 * 32; i += 256) {
            int o = i >> 5, kk = i & 31;
            As[o][kk] = w[(size_t)(o0 + o) * C + c0 + kk];
        }
        for (int i = t; i < 512; i += 256) {
            int kk = i >> 4, q4 = i & 15;
            *(float4*)&Bs[kk][q4 * 4] =
                *(const float4*)&x[(size_t)(c0 + kk) * NN + n0 + q4 * 4];
        }
        __syncthreads();
        #pragma unroll
        for (int kk = 0; kk < 32; kk++) {
            float a0 = As[ty * 4 + 0][kk];
            float a1 = As[ty * 4 + 1][kk];
            float a2 = As[ty * 4 + 2][kk];
            float a3 = As[ty * 4 + 3][kk];
            float4 bv4 = *(float4*)&Bs[kk][tx * 4];
            acc[0][0] += a0 * bv4.x; acc[0][1] += a0 * bv4.y; acc[0][2] += a0 * bv4.z; acc[0][3] += a0 * bv4.w;
            acc[1][0] += a1 * bv4.x; acc[1][1] += a1 * bv4.y; acc[1][2] += a1 * bv4.z; acc[1][3] += a1 * bv4.w;
            acc[2][0] += a2 * bv4.x; acc[2][1] += a2 * bv4.y; acc[2][2] += a2 * bv4.z; acc[2][3] += a2 * bv4.w;
            acc[3][0] += a3 * bv4.x; acc[3][1] += a3 * bv4.y; acc[3][2] += a3 * bv4.z; acc[3][3] += a3 * bv4.w;
        }
        __syncthreads();
    }
    #pragma unroll
    for (int i = 0; i < 4; i++) {
        int oo = o0 + ty * 4 + i;
        float bi = bias[oo];
        float4 r = make_float4(acc[i][0] + bi, acc[i][1] + bi,
                               acc[i][2] + bi, acc[i][3] + bi);
        *(float4*)&y[(size_t)oo * NN + n0 + tx * 4] = r;
    }
}

// ---------------------------------------------------------------------------
// Flash attention: one block = 64 queries for one (branch, batch, head).
// Online softmax over 64 key tiles of 64 keys. 256 threads = 8 warps,
// each warp owns 8 query rows; lane owns output dim d = lane.
// grid: (64 qtiles, 8 heads, 4) with z = branch*2 + b
// ---------------------------------------------------------------------------
__global__ void attn_kernel()
{
    int qt = blockIdx.x;
    int h  = blockIdx.y;
    int zb = blockIdx.z;
    int b  = zb & 1, br = zb >> 1;
    int qsrc = br;        // branch 0: q from spatial; branch 1: q from freq
    int ksrc = br ^ 1;

    const float* Q = &g_qkv[qsrc][b][0][h * HD][0];
    const float* K = &g_qkv[ksrc][b][1][h * HD][0];
    const float* V = &g_qkv[ksrc][b][2][h * HD][0];
    float* Out = &g_attn[br][b][h * HD][0];

    __shared__ float Qs[HD][64];
    __shared__ float Ks[HD][64];
    __shared__ float Vs[64][HD + 1];
    __shared__ float Ps[64][64];   // P tile; reused as O staging at the end

    int t = threadIdx.x;
    int lane = t & 31, w = t >> 5;
    int r0 = w * 8;
    int n0 = qt * 64;

    for (int i = t; i < HD * 64; i += 256) {
        int d = i >> 6, m = i & 63;
        Qs[d][m] = Q[(size_t)d * NN + n0 + m];
    }

    float o[8] = {};
    float m_i[8], l_i[8];
    #pragma unroll
    for (int i = 0; i < 8; i++) { m_i[i] = -1e30f; l_i[i] = 0.f; }

    __syncthreads();

    for (int kt = 0; kt < 64; kt++) {
        for (int i = t; i < HD * 64; i += 256) {
            int d = i >> 6, n = i & 63;
            Ks[d][n] = K[(size_t)d * NN + kt * 64 + n];
        }
        for (int i = t; i < HD * 64; i += 256) {
            int d = i >> 6, n = i & 63;
            Vs[n][d] = V[(size_t)d * NN + kt * 64 + n];
        }
        __syncthreads();

        // S = Q^T K : lane holds keys (lane, lane+32) for its warp's 8 rows
        float s0[8] = {}, s1[8] = {};
        #pragma unroll 8
        for (int d = 0; d < HD; d++) {
            float k0 = Ks[d][lane], k1 = Ks[d][lane + 32];
            #pragma unroll
            for (int i = 0; i < 8; i++) {
                float qv = Qs[d][r0 + i];
                s0[i] += qv * k0;
                s1[i] += qv * k1;
            }
        }

        // online softmax per row
        #pragma unroll
        for (int i = 0; i < 8; i++) {
            float a = s0[i] * ATT_SCALE, c = s1[i] * ATT_SCALE;
            float tm = fmaxf(a, c);
            #pragma unroll
            for (int off = 16; off; off >>= 1)
                tm = fmaxf(tm, __shfl_xor_sync(0xffffffffu, tm, off));
            float mn = fmaxf(m_i[i], tm);
            float p0 = __expf(a - mn), p1 = __expf(c - mn);
            float rs = p0 + p1;
            #pragma unroll
            for (int off = 16; off; off >>= 1)
                rs += __shfl_xor_sync(0xffffffffu, rs, off);
            float alpha = __expf(m_i[i] - mn);
            l_i[i] = l_i[i] * alpha + rs;
            m_i[i] = mn;
            o[i] *= alpha;
            Ps[r0 + i][lane] = p0;
            Ps[r0 + i][lane + 32] = p1;
        }
        __syncwarp();

        // O += P @ V : lane owns dim d = lane
        #pragma unroll 4
        for (int n = 0; n < 64; n++) {
            float vv = Vs[n][lane];
            #pragma unroll
            for (int i = 0; i < 8; i++)
                o[i] += Ps[r0 + i][n] * vv;
        }
        __syncthreads();
    }

    // normalize, transpose through smem (reuse Ps), coalesced store
    float* Osm = &Ps[0][0];   // needs 32*65 = 2080 floats <= 4096
    #pragma unroll
    for (int i = 0; i < 8; i++)
        Osm[lane * 65 + r0 + i] = o[i] / l_i[i];
    __syncthreads();
    for (int i = t; i < HD * 64; i += 256) {
        int d = i >> 6, r = i & 63;
        Out[(size_t)d * NN + n0 + r] = Osm[d * 65 + r];
    }
}

// ---------------------------------------------------------------------------
// Output: out = spatial + freq + 2*bo + wo @ (attn_branch0 + attn_branch1)
// grid: (N/64, C/64, 2 batches)
// ---------------------------------------------------------------------------
__global__ void out_kernel(const float* __restrict__ xs,
                           const float* __restrict__ xf,
                           const float* __restrict__ wo,
                           const float* __restrict__ bo,
                           float* __restrict__ out)
{
    int b  = blockIdx.z;
    int o0 = blockIdx.y * 64;
    int n0 = blockIdx.x * 64;
    const float* a1 = &g_attn[0][b][0][0];
    const float* a2 = &g_attn[1][b][0][0];

    __shared__ float As[64][33];
    __shared__ float Bs[32][64];

    int t  = threadIdx.x;
    int tx = t & 15, ty = t >> 4;
    float acc[4][4] = {};

    for (int c0 = 0; c0 < C; c0 += 32) {
        for (int i = t; i < 64 * 32; i += 256) {
            int o = i >> 5, kk = i & 31;
            As[o][kk] = wo[(size_t)(o0 + o) * C + c0 + kk];
        }
        for (int i = t; i < 512; i += 256) {
            int kk = i >> 4, q4 = i & 15;
            size_t off = (size_t)(c0 + kk) * NN + n0 + q4 * 4;
            float4 u = *(const float4*)&a1[off];
            float4 v = *(const float4*)&a2[off];
            u.x += v.x; u.y += v.y; u.z += v.z; u.w += v.w;
            *(float4*)&Bs[kk][q4 * 4] = u;
        }
        __syncthreads();
        #pragma unroll
        for (int kk = 0; kk < 32; kk++) {
            float a0 = As[ty * 4 + 0][kk];
            float a1v = As[ty * 4 + 1][kk];
            float a2v = As[ty * 4 + 2][kk];
            float a3 = As[ty * 4 + 3][kk];
            float4 bv4 = *(float4*)&Bs[kk][tx * 4];
            acc[0][0] += a0 * bv4.x;  acc[0][1] += a0 * bv4.y;  acc[0][2] += a0 * bv4.z;  acc[0][3] += a0 * bv4.w;
            acc[1][0] += a1v * bv4.x; acc[1][1] += a1v * bv4.y; acc[1][2] += a1v * bv4.z; acc[1][3] += a1v * bv4.w;
            acc[2][0] += a2v * bv4.x; acc[2][1] += a2v * bv4.y; acc[2][2] += a2v * bv4.z; acc[2][3] += a2v * bv4.w;
            acc[3][0] += a3 * bv4.x;  acc[3][1] += a3 * bv4.y;  acc[3][2] += a3 * bv4.z;  acc[3][3] += a3 * bv4.w;
        }
        __syncthreads();
    }

    size_t base = (size_t)b * C * NN;
    #pragma unroll
    for (int i = 0; i < 4; i++) {
        int oo = o0 + ty * 4 + i;
        float bi = 2.0f * bo[oo];
        size_t off = base + (size_t)oo * NN + n0 + tx * 4;
        float4 s = *(const float4*)&xs[off];
        float4 f = *(const float4*)&xf[off];
        float4 r;
        r.x = acc[i][0] + bi + s.x + f.x;
        r.y = acc[i][1] + bi + s.y + f.y;
        r.z = acc[i][2] + bi + s.z + f.z;
        r.w = acc[i][3] + bi + s.w + f.w;
        *(float4*)&out[off] = r;
    }
}

extern "C" void kernel_launch(void* const* d_in, const int* in_sizes, int n_in,
                              void* d_out, int out_size)
{
    const float* xs = (const float*)d_in[0];
    const float* xf = (const float*)d_in[1];
    const float* wq = (const float*)d_in[2];
    const float* bq = (const float*)d_in[3];
    const float* wk = (const float*)d_in[4];
    const float* bk = (const float*)d_in[5];
    const float* wv = (const float*)d_in[6];
    const float* bv = (const float*)d_in[7];
    const float* wo = (const float*)d_in[8];
    const float* bo = (const float*)d_in[9];
    float* out = (float*)d_out;

    proj_kernel<<<dim3(64, 4, 12), 256>>>(xs, xf, wq, bq, wk, bk, wv, bv);
    attn_kernel<<<dim3(64, 8, 4), 256>>>();
    out_kernel<<<dim3(64, 4, 2), 256>>>(xs, xf, wo, bo, out);
}

// round 3
// speedup vs baseline: 2.1097x; 2.1097x over previous
#include <cuda_runtime.h>
#include <cuda_fp16.h>

#define BB 2
#define C 256
#define NH 8
#define HD 32
#define NN 4096
// 32^-0.5 * log2(e)
#define SCLOG2 0.2550348655f

__device__ float g_qkv[2][BB][3][C][NN];
__device__ float g_attn[2][BB][C][NN];

__device__ __forceinline__ unsigned f2tf(float x) {
    unsigned u; asm("cvt.rna.tf32.f32 %0, %1;" : "=r"(u) : "f"(x)); return u;
}
__device__ __forceinline__ float fex2(float x) {
    float y; asm("ex2.approx.ftz.f32 %0, %1;" : "=f"(y) : "f"(x)); return y;
}
__device__ __forceinline__ unsigned h2bits(float lo, float hi) {
    __half2 h = __floats2half2_rn(lo, hi);
    return *(unsigned*)&h;
}
__device__ __forceinline__ void mma_tf32(float* d, const unsigned* a, unsigned b0, unsigned b1) {
    asm volatile(
        "mma.sync.aligned.m16n8k8.row.col.f32.tf32.tf32.f32 "
        "{%0,%1,%2,%3},{%4,%5,%6,%7},{%8,%9},{%0,%1,%2,%3};"
        : "+f"(d[0]), "+f"(d[1]), "+f"(d[2]), "+f"(d[3])
        : "r"(a[0]), "r"(a[1]), "r"(a[2]), "r"(a[3]), "r"(b0), "r"(b1));
}
__device__ __forceinline__ void mma_f16(float* d, unsigned a0, unsigned a1, unsigned a2,
                                        unsigned a3, unsigned b0, unsigned b1) {
    asm volatile(
        "mma.sync.aligned.m16n8k16.row.col.f32.f16.f16.f32 "
        "{%0,%1,%2,%3},{%4,%5,%6,%7},{%8,%9},{%0,%1,%2,%3};"
        : "+f"(d[0]), "+f"(d[1]), "+f"(d[2]), "+f"(d[3])
        : "r"(a0), "r"(a1), "r"(a2), "r"(a3), "r"(b0), "r"(b1));
}

// ---------------------------------------------------------------------------
// Projection GEMM: Y[o,n] = sum_c W[o,c] * X[c,n] + bias[o]
// 64x64 tile per block, 256 threads, 4x4 microtile, K-chunk 32.
// grid: (N/64, C/64, 12)
// ---------------------------------------------------------------------------
__global__ void proj_kernel(const float* __restrict__ xs,
                            const float* __restrict__ xf,
                            const float* __restrict__ wq, const float* __restrict__ bq,
                            const float* __restrict__ wk, const float* __restrict__ bk,
                            const float* __restrict__ wv, const float* __restrict__ bv)
{
    int zz = blockIdx.z;
    int plane = zz % 3;
    int sb = zz / 3;
    int b = sb & 1;
    int src = sb >> 1;
    const float* x = (src ? xf : xs) + (size_t)b * C * NN;
    const float* w; const float* bias;
    if (plane == 0)      { w = wq; bias = bq; }
    else if (plane == 1) { w = wk; bias = bk; }
    else                 { w = wv; bias = bv; }
    float* y = &g_qkv[src][b][plane][0][0];

    int o0 = blockIdx.y * 64;
    int n0 = blockIdx.x * 64;

    __shared__ float As[64][33];
    __shared__ float Bs[32][64];

    int t  = threadIdx.x;
    int tx = t & 15, ty = t >> 4;
    float acc[4][4] = {};

    for (int c0 = 0; c0 < C; c0 += 32) {
        for (int i = t; i < 64 * 32; i += 256) {
            int o = i >> 5, kk = i & 31;
            As[o][kk] = w[(size_t)(o0 + o) * C + c0 + kk];
        }
        for (int i = t; i < 512; i += 256) {
            int kk = i >> 4, q4 = i & 15;
            *(float4*)&Bs[kk][q4 * 4] =
                *(const float4*)&x[(size_t)(c0 + kk) * NN + n0 + q4 * 4];
        }
        __syncthreads();
        #pragma unroll
        for (int kk = 0; kk < 32; kk++) {
            float a0 = As[ty * 4 + 0][kk];
            float a1 = As[ty * 4 + 1][kk];
            float a2 = As[ty * 4 + 2][kk];
            float a3 = As[ty * 4 + 3][kk];
            float4 bv4 = *(float4*)&Bs[kk][tx * 4];
            acc[0][0] += a0 * bv4.x; acc[0][1] += a0 * bv4.y; acc[0][2] += a0 * bv4.z; acc[0][3] += a0 * bv4.w;
            acc[1][0] += a1 * bv4.x; acc[1][1] += a1 * bv4.y; acc[1][2] += a1 * bv4.z; acc[1][3] += a1 * bv4.w;
            acc[2][0] += a2 * bv4.x; acc[2][1] += a2 * bv4.y; acc[2][2] += a2 * bv4.z; acc[2][3] += a2 * bv4.w;
            acc[3][0] += a3 * bv4.x; acc[3][1] += a3 * bv4.y; acc[3][2] += a3 * bv4.z; acc[3][3] += a3 * bv4.w;
        }
        __syncthreads();
    }
    #pragma unroll
    for (int i = 0; i < 4; i++) {
        int oo = o0 + ty * 4 + i;
        float bi = bias[oo];
        float4 r = make_float4(acc[i][0] + bi, acc[i][1] + bi,
                               acc[i][2] + bi, acc[i][3] + bi);
        *(float4*)&y[(size_t)oo * NN + n0 + tx * 4] = r;
    }
}

// ---------------------------------------------------------------------------
// Flash attention on tensor cores.
// Block = 128 queries for one (branch, batch, head); 8 warps x 16 q rows.
// QK^T: tf32 m16n8k8. PV: fp16 m16n8k16 (P reg-resident via C->A layout match).
// grid: (32 qtiles, 8 heads, 4)
// ---------------------------------------------------------------------------
__global__ __launch_bounds__(256) void attn_kernel()
{
    __shared__ float Qst[128 * 36];   // Q^T [q][d], tf32-rounded; reused as Os[32][132]
    __shared__ float Kst[128 * 36];   // K^T [key][d], tf32-rounded
    __shared__ __half Vs[32 * 136];   // V [d][key] fp16

    int qt = blockIdx.x;
    int h  = blockIdx.y;
    int zb = blockIdx.z;
    int b  = zb & 1, br = zb >> 1;
    int qsrc = br, ksrc = br ^ 1;

    const float* Q = &g_qkv[qsrc][b][0][h * HD][0];
    const float* K = &g_qkv[ksrc][b][1][h * HD][0];
    const float* V = &g_qkv[ksrc][b][2][h * HD][0];
    float* Out = &g_attn[br][b][h * HD][0];

    int t = threadIdx.x, lane = t & 31, w = t >> 5;
    int gr = lane >> 2, tc = lane & 3;
    int qb = w * 16;
    int n0 = qt * 128;

    // Q tile: transpose + tf32 round
    for (int i = t; i < 32 * 128; i += 256) {
        int d = i >> 7, q = i & 127;
        Qst[q * 36 + d] = __uint_as_float(f2tf(Q[(size_t)d * NN + n0 + q]));
    }
    __syncthreads();

    // Q fragments resident in registers (a-layout, tf32)
    unsigned aq[4][4];
    #pragma unroll
    for (int kk = 0; kk < 4; kk++) {
        aq[kk][0] = __float_as_uint(Qst[(qb + gr) * 36 + kk * 8 + tc]);
        aq[kk][1] = __float_as_uint(Qst[(qb + gr + 8) * 36 + kk * 8 + tc]);
        aq[kk][2] = __float_as_uint(Qst[(qb + gr) * 36 + kk * 8 + tc + 4]);
        aq[kk][3] = __float_as_uint(Qst[(qb + gr + 8) * 36 + kk * 8 + tc + 4]);
    }

    float o[4][4] = {};
    float m0 = -1e30f, m1 = -1e30f, l0 = 0.f, l1 = 0.f;

    for (int kt = 0; kt < 32; kt++) {
        int k0 = kt * 128;
        __syncthreads();   // previous iter's consumers done
        for (int i = t; i < 32 * 128; i += 256) {
            int d = i >> 7, kq = i & 127;
            Kst[kq * 36 + d] = __uint_as_float(f2tf(K[(size_t)d * NN + k0 + kq]));
        }
        for (int i = t; i < 32 * 64; i += 256) {
            int d = i >> 6, kh = i & 63;
            float2 v2 = *(const float2*)&V[(size_t)d * NN + k0 + 2 * kh];
            *(__half2*)&Vs[d * 136 + 2 * kh] = __floats2half2_rn(v2.x, v2.y);
        }
        __syncthreads();

        // S = Q^T K  (16 key-blocks of 8)
        float s[16][4];
        #pragma unroll
        for (int nb = 0; nb < 16; nb++) { s[nb][0] = 0.f; s[nb][1] = 0.f; s[nb][2] = 0.f; s[nb][3] = 0.f; }

        #pragma unroll 4
        for (int nb = 0; nb < 16; nb++) {
            const float* kr = &Kst[(nb * 8 + gr) * 36];
            #pragma unroll
            for (int kk = 0; kk < 4; kk++) {
                unsigned b0 = __float_as_uint(kr[kk * 8 + tc]);
                unsigned b1 = __float_as_uint(kr[kk * 8 + tc + 4]);
                mma_tf32(s[nb], aq[kk], b0, b1);
            }
        }

        // online softmax (log2 domain, scale folded in)
        float mx0 = -1e30f, mx1 = -1e30f;
        #pragma unroll
        for (int nb = 0; nb < 16; nb++) {
            mx0 = fmaxf(mx0, fmaxf(s[nb][0], s[nb][1]));
            mx1 = fmaxf(mx1, fmaxf(s[nb][2], s[nb][3]));
        }
        mx0 = fmaxf(mx0, __shfl_xor_sync(0xffffffffu, mx0, 1));
        mx0 = fmaxf(mx0, __shfl_xor_sync(0xffffffffu, mx0, 2));
        mx1 = fmaxf(mx1, __shfl_xor_sync(0xffffffffu, mx1, 1));
        mx1 = fmaxf(mx1, __shfl_xor_sync(0xffffffffu, mx1, 2));
        float nm0 = fmaxf(m0, mx0 * SCLOG2);
        float nm1 = fmaxf(m1, mx1 * SCLOG2);
        float al0 = fex2(m0 - nm0), al1 = fex2(m1 - nm1);
        m0 = nm0; m1 = nm1;
        float sum0 = 0.f, sum1 = 0.f;
        #pragma unroll
        for (int nb = 0; nb < 16; nb++) {
            float p0 = fex2(fmaf(s[nb][0], SCLOG2, -nm0));
            float p1 = fex2(fmaf(s[nb][1], SCLOG2, -nm0));
            float p2 = fex2(fmaf(s[nb][2], SCLOG2, -nm1));
            float p3 = fex2(fmaf(s[nb][3], SCLOG2, -nm1));
            sum0 += p0 + p1; sum1 += p2 + p3;
            s[nb][0] = p0; s[nb][1] = p1; s[nb][2] = p2; s[nb][3] = p3;
        }
        sum0 += __shfl_xor_sync(0xffffffffu, sum0, 1);
        sum0 += __shfl_xor_sync(0xffffffffu, sum0, 2);
        sum1 += __shfl_xor_sync(0xffffffffu, sum1, 1);
        sum1 += __shfl_xor_sync(0xffffffffu, sum1, 2);
        l0 = l0 * al0 + sum0;
        l1 = l1 * al1 + sum1;
        #pragma unroll
        for (int dn = 0; dn < 4; dn++) {
            o[dn][0] *= al0; o[dn][1] *= al0; o[dn][2] *= al1; o[dn][3] *= al1;
        }

        // O += P @ V^T : fp16 mma, P packed straight from C fragments
        #pragma unroll
        for (int ks = 0; ks < 8; ks++) {
            unsigned pa0 = h2bits(s[2 * ks][0],     s[2 * ks][1]);
            unsigned pa1 = h2bits(s[2 * ks][2],     s[2 * ks][3]);
            unsigned pa2 = h2bits(s[2 * ks + 1][0], s[2 * ks + 1][1]);
            unsigned pa3 = h2bits(s[2 * ks + 1][2], s[2 * ks + 1][3]);
            int keyh = ks * 8 + tc;   // half2 index: keys ks*16 + 2*tc (+1)
            #pragma unroll
            for (int dn = 0; dn < 4; dn++) {
                int d = dn * 8 + gr;
                unsigned b0 = *(const unsigned*)&Vs[d * 136 + 2 * keyh];
                unsigned b1 = *(const unsigned*)&Vs[d * 136 + 2 * keyh + 8];
                mma_f16(o[dn], pa0, pa1, pa2, pa3, b0, b1);
            }
        }
    }

    // normalize + transpose via smem (reuse Qst), coalesced store
    __syncthreads();
    float* Os = Qst;
    float li0 = 1.0f / l0, li1 = 1.0f / l1;
    #pragma unroll
    for (int dn = 0; dn < 4; dn++) {
        #pragma unroll
        for (int j = 0; j < 4; j++) {
            int d = dn * 8 + 2 * tc + (j & 1);
            int q = qb + gr + ((j >> 1) ? 8 : 0);
            Os[d * 132 + q] = o[dn][j] * ((j < 2) ? li0 : li1);
        }
    }
    __syncthreads();
    for (int i = t; i < 32 * 128; i += 256) {
        int d = i >> 7, q = i & 127;
        Out[(size_t)d * NN + n0 + q] = Os[d * 132 + q];
    }
}

// ---------------------------------------------------------------------------
// Output: out = spatial + freq + 2*bo + wo @ (attn_branch0 + attn_branch1)
// ---------------------------------------------------------------------------
__global__ void out_kernel(const float* __restrict__ xs,
                           const float* __restrict__ xf,
                           const float* __restrict__ wo,
                           const float* __restrict__ bo,
                           float* __restrict__ out)
{
    int b  = blockIdx.z;
    int o0 = blockIdx.y * 64;
    int n0 = blockIdx.x * 64;
    const float* a1 = &g_attn[0][b][0][0];
    const float* a2 = &g_attn[1][b][0][0];

    __shared__ float As[64][33];
    __shared__ float Bs[32][64];

    int t  = threadIdx.x;
    int tx = t & 15, ty = t >> 4;
    float acc[4][4] = {};

    for (int c0 = 0; c0 < C; c0 += 32) {
        for (int i = t; i < 64 * 32; i += 256) {
            int o = i >> 5, kk = i & 31;
            As[o][kk] = wo[(size_t)(o0 + o) * C + c0 + kk];
        }
        for (int i = t; i < 512; i += 256) {
            int kk = i >> 4, q4 = i & 15;
            size_t off = (size_t)(c0 + kk) * NN + n0 + q4 * 4;
            float4 u = *(const float4*)&a1[off];
            float4 v = *(const float4*)&a2[off];
            u.x += v.x; u.y += v.y; u.z += v.z; u.w += v.w;
            *(float4*)&Bs[kk][q4 * 4] = u;
        }
        __syncthreads();
        #pragma unroll
        for (int kk = 0; kk < 32; kk++) {
            float a0  = As[ty * 4 + 0][kk];
            float a1v = As[ty * 4 + 1][kk];
            float a2v = As[ty * 4 + 2][kk];
            float a3  = As[ty * 4 + 3][kk];
            float4 bv4 = *(float4*)&Bs[kk][tx * 4];
            acc[0][0] += a0 * bv4.x;  acc[0][1] += a0 * bv4.y;  acc[0][2] += a0 * bv4.z;  acc[0][3] += a0 * bv4.w;
            acc[1][0] += a1v * bv4.x; acc[1][1] += a1v * bv4.y; acc[1][2] += a1v * bv4.z; acc[1][3] += a1v * bv4.w;
            acc[2][0] += a2v * bv4.x; acc[2][1] += a2v * bv4.y; acc[2][2] += a2v * bv4.z; acc[2][3] += a2v * bv4.w;
            acc[3][0] += a3 * bv4.x;  acc[3][1] += a3 * bv4.y;  acc[3][2] += a3 * bv4.z;  acc[3][3] += a3 * bv4.w;
        }
        __syncthreads();
    }

    size_t base = (size_t)b * C * NN;
    #pragma unroll
    for (int i = 0; i < 4; i++) {
        int oo = o0 + ty * 4 + i;
        float bi = 2.0f * bo[oo];
        size_t off = base + (size_t)oo * NN + n0 + tx * 4;
        float4 s = *(const float4*)&xs[off];
        float4 f = *(const float4*)&xf[off];
        float4 r;
        r.x = acc[i][0] + bi + s.x + f.x;
        r.y = acc[i][1] + bi + s.y + f.y;
        r.z = acc[i][2] + bi + s.z + f.z;
        r.w = acc[i][3] + bi + s.w + f.w;
        *(float4*)&out[off] = r;
    }
}

extern "C" void kernel_launch(void* const* d_in, const int* in_sizes, int n_in,
                              void* d_out, int out_size)
{
    const float* xs = (const float*)d_in[0];
    const float* xf = (const float*)d_in[1];
    const float* wq = (const float*)d_in[2];
    const float* bq = (const float*)d_in[3];
    const float* wk = (const float*)d_in[4];
    const float* bk = (const float*)d_in[5];
    const float* wv = (const float*)d_in[6];
    const float* bv = (const float*)d_in[7];
    const float* wo = (const float*)d_in[8];
    const float* bo = (const float*)d_in[9];
    float* out = (float*)d_out;

    proj_kernel<<<dim3(64, 4, 12), 256>>>(xs, xf, wq, bq, wk, bk, wv, bv);
    attn_kernel<<<dim3(32, 8, 4), 256>>>();
    out_kernel<<<dim3(64, 4, 2), 256>>>(xs, xf, wo, bo, out);
}